// round 3
// baseline (speedup 1.0000x reference)
#include <cuda_runtime.h>

// Problem constants
#define NBATCH   4096
#define TT       256
#define NSTEPS   255   // T-1
#define ND       16
#define SD       8
#define HH       64
#define INX      24    // SD + ND
#define KIN      88    // INX + HH
#define G4       256   // 4*HH
#define NB       32    // batch rows per CTA (16 pairs)
#define NPAIR    16
#define KPAD     90    // xP row length (even, 16B-aligned rows)
#define OPAD     66    // a1P/a2P row length (even, 16B-aligned rows)
#define NTHREADS 512

typedef unsigned long long u64;

struct __align__(16) Smem {
    float2 xP[NPAIR][KPAD];    // pair-packed input: k rows 0..7 x, 8..23 noise, 24..87 h
    float2 zP[NPAIR][G4];      // pair-packed gate pre-activations
    float2 a1P[2][NPAIR][OPAD];
    float2 a2P[2][NPAIR][OPAD];
    float  w1s[2][HH][HH];
    float  w2s[2][HH][HH];
    float  w3s[HH][2][SD];
    float  b1[2][HH];
    float  b2[2][HH];
    float  b3[2][SD];
};

// ---- packed f32x2 helpers ----
__device__ __forceinline__ u64 pk2(float a, float b) {
    u64 r; asm("mov.b64 %0, {%1, %2};" : "=l"(r) : "f"(a), "f"(b)); return r;
}
__device__ __forceinline__ void upk2(u64 v, float& a, float& b) {
    asm("mov.b64 {%0, %1}, %2;" : "=f"(a), "=f"(b) : "l"(v));
}
__device__ __forceinline__ u64 fma2(u64 a, u64 b, u64 c) {
    u64 d; asm("fma.rn.f32x2 %0, %1, %2, %3;" : "=l"(d) : "l"(a), "l"(b), "l"(c)); return d;
}

__device__ __forceinline__ float sigm(float x) {
    return __fdividef(1.f, 1.f + __expf(-x));
}
__device__ __forceinline__ float ftanh(float x) {
    float a = fabsf(x);
    float e = __expf(2.f * a);
    float r = 1.f - __fdividef(2.f, e + 1.f);
    return copysignf(r, x);
}

__global__ __launch_bounds__(NTHREADS, 1)
void genlstm_kernel(
    const float* __restrict__ g_noise, const float* __restrict__ g_eps,
    const float* __restrict__ Wx, const float* __restrict__ Wh, const float* __restrict__ b_g,
    const float* __restrict__ Wm1, const float* __restrict__ bm1,
    const float* __restrict__ Wm2, const float* __restrict__ bm2,
    const float* __restrict__ Wm3, const float* __restrict__ bm3,
    const float* __restrict__ Wv1, const float* __restrict__ bv1,
    const float* __restrict__ Wv2, const float* __restrict__ bv2,
    const float* __restrict__ Wv3, const float* __restrict__ bv3,
    float* __restrict__ g_out)
{
    extern __shared__ float smraw[];
    Smem* sm = reinterpret_cast<Smem*>(smraw);
    const int tid = threadIdx.x;
    const int b0  = blockIdx.x * NB;

    // ---- Phase A weights: registers, loop-invariant across all steps ----
    const int cA  = tid & 255;    // z column = gate*64 + u
    const int pA0 = (tid >> 8) * 8;  // batch-half: pairs pA0..pA0+7
    float wreg[KIN];
#pragma unroll
    for (int k = 0; k < INX; k++) wreg[k] = Wx[k * G4 + cA];
#pragma unroll
    for (int k = 0; k < HH; k++) wreg[INX + k] = Wh[k * G4 + cA];
    const float breg = b_g[cA];

    // ---- MLP weights -> smem ----
    for (int i = tid; i < HH * HH; i += NTHREADS) {
        int r = i >> 6, c = i & 63;
        sm->w1s[0][r][c] = Wm1[i]; sm->w1s[1][r][c] = Wv1[i];
        sm->w2s[0][r][c] = Wm2[i]; sm->w2s[1][r][c] = Wv2[i];
    }
    for (int i = tid; i < HH * SD; i += NTHREADS) {
        int r = i >> 3, c = i & 7;
        sm->w3s[r][0][c] = Wm3[i]; sm->w3s[r][1][c] = Wv3[i];
    }
    if (tid < HH) {
        sm->b1[0][tid] = bm1[tid]; sm->b1[1][tid] = bv1[tid];
        sm->b2[0][tid] = bm2[tid]; sm->b2[1][tid] = bv2[tid];
    }
    if (tid < SD) { sm->b3[0][tid] = bm3[tid]; sm->b3[1][tid] = bv3[tid]; }
    for (int i = tid; i < NPAIR * KPAD; i += NTHREADS)
        sm->xP[i / KPAD][i % KPAD] = make_float2(0.f, 0.f);

    // ---- thread roles ----
    const int uE  = tid & 63;           // elementwise: hidden unit
    const int pqE = tid >> 6;           // elementwise: pair-group (2 pairs)
    const int oB  = tid & 63;           // MLP L1/L2: output unit
    const int pB  = (tid >> 6) & 1;     // path 0=mu 1=var
    const int prB = (tid >> 7) * 4;     // 4 pairs
    const int dD  = tid & 7;            // D/E (tid<128): series dim
    const int prD = tid >> 3;           // D/E: pair
    const int n0  = 2 * prD, n1 = 2 * prD + 1;

    // init: out[:,0,:]=0 and stage noise for step 0 (tid<128)
    if (tid < 128) {
        g_out[((size_t)(b0 + n0) * TT) * SD + dD] = 0.f;
        g_out[((size_t)(b0 + n1) * TT) * SD + dD] = 0.f;
        float2 na = *(const float2*)&g_noise[((size_t)(b0 + n0) * NSTEPS) * ND + 2 * dD];
        float2 nb = *(const float2*)&g_noise[((size_t)(b0 + n1) * NSTEPS) * ND + 2 * dD];
        sm->xP[prD][SD + 2 * dD]     = make_float2(na.x, nb.x);
        sm->xP[prD][SD + 2 * dD + 1] = make_float2(na.y, nb.y);
    }

    float cst[4];  // cell state: 2 pairs x 2 lanes (elementwise role)
#pragma unroll
    for (int q = 0; q < 4; q++) cst[q] = 0.f;
    float cum0 = 0.f, cum1 = 0.f;   // cumsum (D/E role, tid<128)

    for (int s = 0; s < NSTEPS; s++) {
        __syncthreads();   // xP (x, noise, h) complete

        // ==== Phase A: z = [x,n,h] @ W + b  (register weights, FFMA2) ====
        u64 acc[8];
        {
            u64 bb = pk2(breg, breg);
#pragma unroll
            for (int p = 0; p < 8; p++) acc[p] = bb;
        }
#pragma unroll
        for (int k2 = 0; k2 < KIN / 2; k2++) {
            u64 wa = pk2(wreg[2 * k2], wreg[2 * k2]);
            u64 wb = pk2(wreg[2 * k2 + 1], wreg[2 * k2 + 1]);
#pragma unroll
            for (int p = 0; p < 8; p++) {
                float4 xx = *(const float4*)&sm->xP[pA0 + p][2 * k2];
                acc[p] = fma2(wa, pk2(xx.x, xx.y), acc[p]);
                acc[p] = fma2(wb, pk2(xx.z, xx.w), acc[p]);
            }
        }
#pragma unroll
        for (int p = 0; p < 8; p++) {
            float z0, z1; upk2(acc[p], z0, z1);
            sm->zP[pA0 + p][cA] = make_float2(z0, z1);
        }
        __syncthreads();   // zP ready; all xP reads done

        // prefetch eps / next-step noise (D/E threads); hides LDG behind elem+B+C
        float eps0 = 0.f, eps1 = 0.f;
        float2 nza = make_float2(0.f, 0.f), nzb = make_float2(0.f, 0.f);
        if (tid < 128) {
            eps0 = g_eps[((size_t)(b0 + n0) * NSTEPS + s) * SD + dD];
            eps1 = g_eps[((size_t)(b0 + n1) * NSTEPS + s) * SD + dD];
            if (s + 1 < NSTEPS) {
                nza = *(const float2*)&g_noise[((size_t)(b0 + n0) * NSTEPS + (s + 1)) * ND + 2 * dD];
                nzb = *(const float2*)&g_noise[((size_t)(b0 + n1) * NSTEPS + (s + 1)) * ND + 2 * dD];
            }
        }

        // ==== LSTM elementwise: c in regs, h -> xP rows 24..87 ====
#pragma unroll
        for (int q = 0; q < 2; q++) {
            int pp = 2 * pqE + q;
            float2 zi = sm->zP[pp][uE];
            float2 zf = sm->zP[pp][uE + 64];
            float2 zg = sm->zP[pp][uE + 128];
            float2 zo = sm->zP[pp][uE + 192];
            float c0 = sigm(zf.x) * cst[2 * q]     + sigm(zi.x) * ftanh(zg.x);
            float c1 = sigm(zf.y) * cst[2 * q + 1] + sigm(zi.y) * ftanh(zg.y);
            cst[2 * q] = c0; cst[2 * q + 1] = c1;
            float h0 = sigm(zo.x) * ftanh(c0);
            float h1 = sigm(zo.y) * ftanh(c1);
            sm->xP[pp][INX + uE] = make_float2(h0, h1);
        }
        __syncthreads();   // h ready

        // ==== Phase B: MLP layer 1 ====
        {
            u64 acc1[4];
            {
                float bb = sm->b1[pB][oB];
                u64 b2v = pk2(bb, bb);
#pragma unroll
                for (int p = 0; p < 4; p++) acc1[p] = b2v;
            }
#pragma unroll 4
            for (int k2 = 0; k2 < HH / 2; k2++) {
                float wa = sm->w1s[pB][2 * k2][oB];
                float wb = sm->w1s[pB][2 * k2 + 1][oB];
                u64 wwa = pk2(wa, wa), wwb = pk2(wb, wb);
#pragma unroll
                for (int p = 0; p < 4; p++) {
                    float4 xx = *(const float4*)&sm->xP[prB + p][INX + 2 * k2];
                    acc1[p] = fma2(wwa, pk2(xx.x, xx.y), acc1[p]);
                    acc1[p] = fma2(wwb, pk2(xx.z, xx.w), acc1[p]);
                }
            }
#pragma unroll
            for (int p = 0; p < 4; p++) {
                float v0, v1; upk2(acc1[p], v0, v1);
                sm->a1P[pB][prB + p][oB] = make_float2(fmaxf(v0, 0.f), fmaxf(v1, 0.f));
            }
        }
        __syncthreads();

        // ==== Phase C: MLP layer 2 ====
        {
            u64 acc2[4];
            {
                float bb = sm->b2[pB][oB];
                u64 b2v = pk2(bb, bb);
#pragma unroll
                for (int p = 0; p < 4; p++) acc2[p] = b2v;
            }
#pragma unroll 4
            for (int k2 = 0; k2 < HH / 2; k2++) {
                float wa = sm->w2s[pB][2 * k2][oB];
                float wb = sm->w2s[pB][2 * k2 + 1][oB];
                u64 wwa = pk2(wa, wa), wwb = pk2(wb, wb);
#pragma unroll
                for (int p = 0; p < 4; p++) {
                    float4 xx = *(const float4*)&sm->a1P[pB][prB + p][2 * k2];
                    acc2[p] = fma2(wwa, pk2(xx.x, xx.y), acc2[p]);
                    acc2[p] = fma2(wwb, pk2(xx.z, xx.w), acc2[p]);
                }
            }
#pragma unroll
            for (int p = 0; p < 4; p++) {
                float v0, v1; upk2(acc2[p], v0, v1);
                sm->a2P[pB][prB + p][oB] = make_float2(fmaxf(v0, 0.f), fmaxf(v1, 0.f));
            }
        }
        __syncthreads();   // a2P ready

        // ==== Phase D+E (tid<128): L3 both paths, sample, cumsum, store, stage x ====
        if (tid < 128) {
            u64 am = pk2(sm->b3[0][dD], sm->b3[0][dD]);
            u64 av = pk2(sm->b3[1][dD], sm->b3[1][dD]);
#pragma unroll 8
            for (int k = 0; k < HH; k++) {
                float2 xm = sm->a2P[0][prD][k];
                float2 xv = sm->a2P[1][prD][k];
                float wm = sm->w3s[k][0][dD];
                float wv = sm->w3s[k][1][dD];
                am = fma2(pk2(wm, wm), pk2(xm.x, xm.y), am);
                av = fma2(pk2(wv, wv), pk2(xv.x, xv.y), av);
            }
            float mu0, mu1, v0, v1;
            upk2(am, mu0, mu1); upk2(av, v0, v1);
            float x0 = fmaf(__expf(0.5f * v0), eps0, mu0);
            float x1 = fmaf(__expf(0.5f * v1), eps1, mu1);
            cum0 += x0; cum1 += x1;
            g_out[((size_t)(b0 + n0) * TT + (s + 1)) * SD + dD] = cum0;
            g_out[((size_t)(b0 + n1) * TT + (s + 1)) * SD + dD] = cum1;
            sm->xP[prD][dD] = make_float2(x0, x1);
            if (s + 1 < NSTEPS) {
                sm->xP[prD][SD + 2 * dD]     = make_float2(nza.x, nzb.x);
                sm->xP[prD][SD + 2 * dD + 1] = make_float2(nza.y, nzb.y);
            }
        }
        // loop-top __syncthreads guards xP writes
    }
}

extern "C" void kernel_launch(void* const* d_in, const int* in_sizes, int n_in,
                              void* d_out, int out_size) {
    const float* noise = (const float*)d_in[0];
    const float* eps   = (const float*)d_in[1];
    const float* Wx    = (const float*)d_in[2];
    const float* Wh    = (const float*)d_in[3];
    const float* b     = (const float*)d_in[4];
    const float* Wm1   = (const float*)d_in[5];
    const float* bm1   = (const float*)d_in[6];
    const float* Wm2   = (const float*)d_in[7];
    const float* bm2   = (const float*)d_in[8];
    const float* Wm3   = (const float*)d_in[9];
    const float* bm3   = (const float*)d_in[10];
    const float* Wv1   = (const float*)d_in[11];
    const float* bv1   = (const float*)d_in[12];
    const float* Wv2   = (const float*)d_in[13];
    const float* bv2   = (const float*)d_in[14];
    const float* Wv3   = (const float*)d_in[15];
    const float* bv3   = (const float*)d_in[16];
    float* out = (float*)d_out;

    const int smem_bytes = (int)sizeof(Smem);
    cudaFuncSetAttribute(genlstm_kernel,
                         cudaFuncAttributeMaxDynamicSharedMemorySize, smem_bytes);

    genlstm_kernel<<<NBATCH / NB, NTHREADS, smem_bytes>>>(
        noise, eps, Wx, Wh, b,
        Wm1, bm1, Wm2, bm2, Wm3, bm3,
        Wv1, bv1, Wv2, bv2, Wv3, bv3,
        out);
}

// round 4
// speedup vs baseline: 1.4543x; 1.4543x over previous
#include <cuda_runtime.h>

#define NBATCH   4096
#define TT       256
#define NSTEPS   255
#define ND       16
#define SD       8
#define HH       64
#define INX      24    // SD + ND
#define KIN      88    // INX + HH
#define G4       256
#define NB       32    // batch rows per CTA
#define XPAD     36    // xB row stride (floats): 144B, 16B-aligned
#define A2PAD    33    // a2 row stride (float2)
#define NTHREADS 512

typedef unsigned long long u64;

struct __align__(16) Smem {
    float4 wz4[KIN][HH];     // (wi,wf,wg,wo) per (k, unit)
    float2 w1p[HH][HH];      // (wmu, wvar) per (k, out)
    float2 w2p[HH][HH];
    float2 w3p[HH][SD];
    float4 bz4[HH];          // (bi,bf,bg,bo)
    float2 b1p[HH];
    float2 b2p[HH];
    float2 b3p[SD];
    float  xB[KIN][XPAD];    // rows 0..7 x, 8..23 noise, 24..87 h ; col = belem
    union U {
        struct Z { u64 zIF[NB][HH]; u64 zGO[NB][HH]; } z;           // gate pre-acts
        struct A { float2 a1[NB][HH]; float2 a2[HH][A2PAD]; } a;    // MLP activations
    } u;
    float epsS[NB][SD];      // staged eps(s)
};

// ---- packed f32x2 helpers ----
__device__ __forceinline__ u64 pk2(float a, float b) {
    u64 r; asm("mov.b64 %0, {%1, %2};" : "=l"(r) : "f"(a), "f"(b)); return r;
}
__device__ __forceinline__ void upk2(u64 v, float& a, float& b) {
    asm("mov.b64 {%0, %1}, %2;" : "=f"(a), "=f"(b) : "l"(v));
}
__device__ __forceinline__ u64 fma2(u64 a, u64 b, u64 c) {
    u64 d; asm("fma.rn.f32x2 %0, %1, %2, %3;" : "=l"(d) : "l"(a), "l"(b), "l"(c)); return d;
}

__device__ __forceinline__ float sigm(float x) {
    return __fdividef(1.f, 1.f + __expf(-x));
}
__device__ __forceinline__ float ftanh(float x) {
    float a = fabsf(x);
    float e = __expf(2.f * a);
    float r = 1.f - __fdividef(2.f, e + 1.f);
    return copysignf(r, x);
}

__global__ __launch_bounds__(NTHREADS, 1)
void genlstm_kernel(
    const float* __restrict__ g_noise, const float* __restrict__ g_eps,
    const float* __restrict__ Wx, const float* __restrict__ Wh, const float* __restrict__ b_g,
    const float* __restrict__ Wm1, const float* __restrict__ bm1,
    const float* __restrict__ Wm2, const float* __restrict__ bm2,
    const float* __restrict__ Wm3, const float* __restrict__ bm3,
    const float* __restrict__ Wv1, const float* __restrict__ bv1,
    const float* __restrict__ Wv2, const float* __restrict__ bv2,
    const float* __restrict__ Wv3, const float* __restrict__ bv3,
    float* __restrict__ g_out)
{
    extern __shared__ float smraw[];
    Smem* sm = reinterpret_cast<Smem*>(smraw);
    const int tid = threadIdx.x;
    const int b0  = blockIdx.x * NB;

    // ================= one-time staging =================
    // LSTM weights gate-interleaved: wz4[k][u] = (W[k][u], W[k][64+u], W[k][128+u], W[k][192+u])
    for (int i = tid; i < KIN * G4; i += NTHREADS) {
        int k = i >> 8, r = i & 255, uu = r >> 2, g = r & 3;
        float v = (k < INX) ? Wx[k * G4 + g * 64 + uu] : Wh[(k - INX) * G4 + g * 64 + uu];
        reinterpret_cast<float*>(sm->wz4)[k * 256 + uu * 4 + g] = v;
    }
    if (tid < HH) {
        sm->bz4[tid] = make_float4(b_g[tid], b_g[64 + tid], b_g[128 + tid], b_g[192 + tid]);
        sm->b1p[tid] = make_float2(bm1[tid], bv1[tid]);
        sm->b2p[tid] = make_float2(bm2[tid], bv2[tid]);
    }
    if (tid < SD) sm->b3p[tid] = make_float2(bm3[tid], bv3[tid]);
    for (int i = tid; i < HH * HH; i += NTHREADS) {
        int k = i >> 6, o = i & 63;
        sm->w1p[k][o] = make_float2(Wm1[i], Wv1[i]);
        sm->w2p[k][o] = make_float2(Wm2[i], Wv2[i]);
    }
    for (int i = tid; i < HH * SD; i += NTHREADS) {
        int k = i >> 3, d = i & 7;
        sm->w3p[k][d] = make_float2(Wm3[i], Wv3[i]);
    }
    // zero xB (x=0, h=0)
    for (int i = tid; i < KIN * XPAD; i += NTHREADS)
        reinterpret_cast<float*>(sm->xB)[i] = 0.f;
    __syncthreads();
    // stage noise(step 0): 32 belems x 16 nd = 512 slots
    {
        int be = tid >> 4, nd = tid & 15;
        sm->xB[SD + nd][be] = g_noise[((size_t)(b0 + be) * NSTEPS) * ND + nd];
    }
    // out[:,0,:] = 0
    if (tid < 256) {
        int be = tid >> 3, d = tid & 7;
        g_out[((size_t)(b0 + be) * TT) * SD + d] = 0.f;
    }

    // ---- thread roles ----
    const int uA = tid & 63, gA = (tid >> 6) & 3;   // Phase A (tid<256): unit, belem-group(8)
    const int uEw = tid & 63, bgE = tid >> 6;       // elementwise: unit, belem-group(4)
    const int oB = tid & 63, gB = (tid >> 6) & 3;   // Phase B/C (tid<256)
    const int dD = tid & 7,  bqD = tid >> 3;        // Phase D/E (tid<128): dim, belem-pair

    float cst[4];
#pragma unroll
    for (int q = 0; q < 4; q++) cst[q] = 0.f;
    float cum0 = 0.f, cum1 = 0.f;

    for (int s = 0; s < NSTEPS; s++) {
        __syncthreads();   // S1: xB (x, noise, h) complete; a2 reads done

        // ============ Phase A (warps 0-7): z = [x,n,h] @ W + b ============
        if (tid < 256) {
            u64 aIF[8], aGO[8];
            {
                float4 bz = sm->bz4[uA];
                u64 bif = pk2(bz.x, bz.y), bgo = pk2(bz.z, bz.w);
#pragma unroll
                for (int j = 0; j < 8; j++) { aIF[j] = bif; aGO[j] = bgo; }
            }
#pragma unroll 4
            for (int k = 0; k < KIN; k++) {
                float4 w = sm->wz4[k][uA];
                u64 wif = pk2(w.x, w.y), wgo = pk2(w.z, w.w);
                float4 x0 = *(const float4*)&sm->xB[k][gA * 8];
                float4 x1 = *(const float4*)&sm->xB[k][gA * 8 + 4];
                float xv[8] = {x0.x, x0.y, x0.z, x0.w, x1.x, x1.y, x1.z, x1.w};
#pragma unroll
                for (int j = 0; j < 8; j++) {
                    u64 xx = pk2(xv[j], xv[j]);
                    aIF[j] = fma2(wif, xx, aIF[j]);
                    aGO[j] = fma2(wgo, xx, aGO[j]);
                }
            }
#pragma unroll
            for (int j = 0; j < 8; j++) {
                sm->u.z.zIF[gA * 8 + j][uA] = aIF[j];
                sm->u.z.zGO[gA * 8 + j][uA] = aGO[j];
            }
        }
        __syncthreads();   // S2: z ready

        // ============ LSTM elementwise (all 512): c in regs, h -> xB ============
#pragma unroll
        for (int q = 0; q < 4; q++) {
            int be = bgE * 4 + q;
            float zi, zf, zg, zo;
            upk2(sm->u.z.zIF[be][uEw], zi, zf);
            upk2(sm->u.z.zGO[be][uEw], zg, zo);
            float cc = sigm(zf) * cst[q] + sigm(zi) * ftanh(zg);
            cst[q] = cc;
            sm->xB[INX + uEw][be] = sigm(zo) * ftanh(cc);
        }
        __syncthreads();   // S3: h ready; z fully consumed (union flips to a1/a2)

        // ============ Phase B (warps 0-7) | prefetch (warps 8-15) ============
        if (tid < 256) {
            u64 acc[8];
            {
                float2 bb = sm->b1p[oB];
                u64 b2v = pk2(bb.x, bb.y);
#pragma unroll
                for (int j = 0; j < 8; j++) acc[j] = b2v;
            }
#pragma unroll 4
            for (int k = 0; k < HH; k++) {
                float2 w = sm->w1p[k][oB];
                u64 wmv = pk2(w.x, w.y);
                float4 h0 = *(const float4*)&sm->xB[INX + k][gB * 8];
                float4 h1 = *(const float4*)&sm->xB[INX + k][gB * 8 + 4];
                float hv[8] = {h0.x, h0.y, h0.z, h0.w, h1.x, h1.y, h1.z, h1.w};
#pragma unroll
                for (int j = 0; j < 8; j++)
                    acc[j] = fma2(wmv, pk2(hv[j], hv[j]), acc[j]);
            }
#pragma unroll
            for (int j = 0; j < 8; j++) {
                float vm, vv; upk2(acc[j], vm, vv);
                sm->u.a.a1[gB * 8 + j][oB] = make_float2(fmaxf(vm, 0.f), fmaxf(vv, 0.f));
            }
        } else {
            // prefetch: noise(s+1) -> xB rows 8..23 ; eps(s) -> epsS
            int t2 = tid - 256;
            if (s + 1 < NSTEPS) {
#pragma unroll
                for (int r = 0; r < 2; r++) {
                    int idx = t2 * 2 + r, be = idx >> 4, nd = idx & 15;
                    sm->xB[SD + nd][be] =
                        g_noise[((size_t)(b0 + be) * NSTEPS + (s + 1)) * ND + nd];
                }
            }
            int be = t2 >> 3, d = t2 & 7;
            sm->epsS[be][d] = g_eps[((size_t)(b0 + be) * NSTEPS + s) * SD + d];
        }
        __syncthreads();   // S4: a1 ready; epsS + noise staged

        // ============ Phase C (warps 0-7) ============
        if (tid < 256) {
            u64 acc[8];
            {
                float2 bb = sm->b2p[oB];
                u64 b2v = pk2(bb.x, bb.y);
#pragma unroll
                for (int j = 0; j < 8; j++) acc[j] = b2v;
            }
#pragma unroll 2
            for (int k2 = 0; k2 < HH / 2; k2++) {
                float2 wA = sm->w2p[2 * k2][oB];
                float2 wB = sm->w2p[2 * k2 + 1][oB];
                u64 wa = pk2(wA.x, wA.y), wb = pk2(wB.x, wB.y);
#pragma unroll
                for (int j = 0; j < 8; j++) {
                    float4 x = *(const float4*)&sm->u.a.a1[gB * 8 + j][2 * k2];
                    acc[j] = fma2(wa, pk2(x.x, x.y), acc[j]);
                    acc[j] = fma2(wb, pk2(x.z, x.w), acc[j]);
                }
            }
            // store a2 k-major: a2[out][belem]
#pragma unroll
            for (int j = 0; j < 8; j++) {
                float vm, vv; upk2(acc[j], vm, vv);
                sm->u.a.a2[oB][gB * 8 + j] = make_float2(fmaxf(vm, 0.f), fmaxf(vv, 0.f));
            }
        }
        __syncthreads();   // S5: a2 ready

        // ============ Phase D+E (tid<128): L3, sample, cumsum, store ============
        if (tid < 128) {
            float2 b3 = sm->b3p[dD];
            u64 am0 = pk2(b3.x, b3.y), am1 = am0;
#pragma unroll 8
            for (int k = 0; k < HH; k++) {
                float2 w = sm->w3p[k][dD];
                u64 wmv = pk2(w.x, w.y);
                u64 x0 = *(const u64*)&sm->u.a.a2[k][2 * bqD];
                u64 x1 = *(const u64*)&sm->u.a.a2[k][2 * bqD + 1];
                am0 = fma2(wmv, x0, am0);
                am1 = fma2(wmv, x1, am1);
            }
            float mu0, lv0, mu1, lv1;
            upk2(am0, mu0, lv0); upk2(am1, mu1, lv1);
            int be0 = 2 * bqD, be1 = 2 * bqD + 1;
            float x0 = fmaf(__expf(0.5f * lv0), sm->epsS[be0][dD], mu0);
            float x1 = fmaf(__expf(0.5f * lv1), sm->epsS[be1][dD], mu1);
            cum0 += x0; cum1 += x1;
            g_out[((size_t)(b0 + be0) * TT + (s + 1)) * SD + dD] = cum0;
            g_out[((size_t)(b0 + be1) * TT + (s + 1)) * SD + dD] = cum1;
            sm->xB[dD][be0] = x0;
            sm->xB[dD][be1] = x1;
        }
        // loop-top S1 guards xB writes
    }
}

extern "C" void kernel_launch(void* const* d_in, const int* in_sizes, int n_in,
                              void* d_out, int out_size) {
    const float* noise = (const float*)d_in[0];
    const float* eps   = (const float*)d_in[1];
    const float* Wx    = (const float*)d_in[2];
    const float* Wh    = (const float*)d_in[3];
    const float* b     = (const float*)d_in[4];
    const float* Wm1   = (const float*)d_in[5];
    const float* bm1   = (const float*)d_in[6];
    const float* Wm2   = (const float*)d_in[7];
    const float* bm2   = (const float*)d_in[8];
    const float* Wm3   = (const float*)d_in[9];
    const float* bm3   = (const float*)d_in[10];
    const float* Wv1   = (const float*)d_in[11];
    const float* bv1   = (const float*)d_in[12];
    const float* Wv2   = (const float*)d_in[13];
    const float* bv2   = (const float*)d_in[14];
    const float* Wv3   = (const float*)d_in[15];
    const float* bv3   = (const float*)d_in[16];
    float* out = (float*)d_out;

    const int smem_bytes = (int)sizeof(Smem);
    cudaFuncSetAttribute(genlstm_kernel,
                         cudaFuncAttributeMaxDynamicSharedMemorySize, smem_bytes);

    genlstm_kernel<<<NBATCH / NB, NTHREADS, smem_bytes>>>(
        noise, eps, Wx, Wh, b,
        Wm1, bm1, Wm2, bm2, Wm3, bm3,
        Wv1, bv1, Wv2, bv2, Wv3, bv3,
        out);
}